// round 7
// baseline (speedup 1.0000x reference)
#include <cuda_runtime.h>
#include <math.h>

// GRU: T=512, B=64, IC=512, HC=512, L=2
// Per layer (2 kernel launches total -> 4-node graph):
//   xproj  : Ax = X @ W1[:,:512]^T + b1 (1024 cols), Gx = X @ W2[:,:512]^T + b2 (512 cols)
//   persist: all 512 recurrent steps in one launch; 128 co-resident CTAs,
//            recurrent weights resident in smem, grid-wide sense barrier,
//            cross-CTA state via L2 (__stcg/__ldcg).

#define NT 512
#define NB 64
#define NH 512
#define NCTA 128

// ---- scratch (static device arrays; no allocation APIs allowed) ----
__device__ float g_Ax[(size_t)32768 * 1024];  // [T*B, 1024]
__device__ float g_Gx[(size_t)32768 * 512];   // [T*B, 512]
__device__ float g_y1[(size_t)32768 * 512];   // layer-1 output sequence
__device__ float g_h [NB * NH];
__device__ float g_rh[NB * NH];
__device__ float g_z [NB * NH];
__device__ int          g_bar_count = 0;
__device__ volatile int g_bar_sense = 0;

// ---- packed f32x2 helpers (bit-exact IEEE fp32, 2x FFMA rate) ----
__device__ __forceinline__ unsigned long long pk2(float a, float b) {
    unsigned long long r;
    asm("mov.b64 %0, {%1, %2};" : "=l"(r) : "f"(a), "f"(b));
    return r;
}
__device__ __forceinline__ void fma2(unsigned long long& d,
                                     unsigned long long a, unsigned long long b) {
    asm("fma.rn.f32x2 %0, %1, %2, %3;" : "=l"(d) : "l"(a), "l"(b), "l"(d));
}
__device__ __forceinline__ float2 up2(unsigned long long v) {
    float lo, hi;
    asm("mov.b64 {%0, %1}, %2;" : "=f"(lo), "=f"(hi) : "l"(v));
    return make_float2(lo, hi);
}
__device__ __forceinline__ float sigf(float x) { return 1.0f / (1.0f + expf(-x)); }

// ---- grid-wide sense-reversing barrier (all 128 CTAs co-resident) ----
__device__ __forceinline__ void grid_barrier(int target) {
    __syncthreads();
    if (threadIdx.x == 0) {
        __threadfence();
        if (atomicAdd(&g_bar_count, 1) == NCTA - 1) {
            atomicExch(&g_bar_count, 0);
            __threadfence();
            g_bar_sense = target;
        } else {
            while (g_bar_sense != target) { __nanosleep(32); }
        }
        __threadfence();
    }
    __syncthreads();
}

// ---- input projection GEMM: C[32768 x 1536] = X[32768 x 512] @ Wc^T + bias ----
__global__ void xproj_kernel(const float* __restrict__ Xext,
                             const float* __restrict__ W1,
                             const float* __restrict__ W2,
                             const float* __restrict__ b1,
                             const float* __restrict__ b2,
                             int layer, int use_y1) {
    const float* __restrict__ X = use_y1 ? g_y1 : Xext;
    __shared__ float Xs[16][132];
    __shared__ float Ws[16][132];
    int tid = threadIdx.x;
    int tx = tid & 15, ty = tid >> 4;
    int row0 = blockIdx.y * 128;
    int col0 = blockIdx.x * 128;
    const float* W1l = W1 + (size_t)layer * 1024 * 1024;
    const float* W2l = W2 + (size_t)layer * 512 * 1024;

    unsigned long long acc[8][4];
#pragma unroll
    for (int i = 0; i < 8; i++)
#pragma unroll
        for (int j = 0; j < 4; j++) acc[i][j] = 0ull;

    for (int k0 = 0; k0 < 512; k0 += 16) {
#pragma unroll
        for (int u = 0; u < 2; u++) {
            int f = tid + u * 256;
            int r = f >> 2;
            int kq = (f & 3) * 4;
            float4 v = *(const float4*)&X[(size_t)(row0 + r) * 512 + k0 + kq];
            Xs[kq + 0][r] = v.x; Xs[kq + 1][r] = v.y;
            Xs[kq + 2][r] = v.z; Xs[kq + 3][r] = v.w;
        }
#pragma unroll
        for (int u = 0; u < 2; u++) {
            int f = tid + u * 256;
            int j = f >> 2;
            int kq = (f & 3) * 4;
            int jg = col0 + j;
            const float* wp = (jg < 1024) ? (W1l + (size_t)jg * 1024)
                                          : (W2l + (size_t)(jg - 1024) * 1024);
            float4 v = *(const float4*)&wp[k0 + kq];
            Ws[kq + 0][j] = v.x; Ws[kq + 1][j] = v.y;
            Ws[kq + 2][j] = v.z; Ws[kq + 3][j] = v.w;
        }
        __syncthreads();
#pragma unroll
        for (int k = 0; k < 16; k++) {
            float a8[8];
            *(float4*)&a8[0] = *(const float4*)&Xs[k][ty * 8];
            *(float4*)&a8[4] = *(const float4*)&Xs[k][ty * 8 + 4];
            ulonglong2 bA = *(const ulonglong2*)&Ws[k][tx * 8];
            ulonglong2 bB = *(const ulonglong2*)&Ws[k][tx * 8 + 4];
#pragma unroll
            for (int i = 0; i < 8; i++) {
                unsigned long long ai = pk2(a8[i], a8[i]);
                fma2(acc[i][0], ai, bA.x);
                fma2(acc[i][1], ai, bA.y);
                fma2(acc[i][2], ai, bB.x);
                fma2(acc[i][3], ai, bB.y);
            }
        }
        __syncthreads();
    }
#pragma unroll
    for (int i = 0; i < 8; i++) {
        int r = row0 + ty * 8 + i;
#pragma unroll
        for (int jq = 0; jq < 4; jq++) {
            float2 v = up2(acc[i][jq]);
            int c = col0 + tx * 8 + jq * 2;
            if (c < 1024) {
                g_Ax[(size_t)r * 1024 + c]     = v.x + b1[layer * 1024 + c];
                g_Ax[(size_t)r * 1024 + c + 1] = v.y + b1[layer * 1024 + c + 1];
            } else {
                int cc = c - 1024;
                g_Gx[(size_t)r * 512 + cc]     = v.x + b2[layer * 512 + cc];
                g_Gx[(size_t)r * 512 + cc + 1] = v.y + b2[layer * 512 + cc + 1];
            }
        }
    }
}

// ---- persistent recurrent kernel ----
// grid: 128 CTAs = 16 col-groups (cg) x 8 batch-groups (bg); 128 threads/CTA.
// smem floats: w1s 32768 | w2s 16384 | hp 4096 | rp 4096 | red 256 = 57600 (230400 B)
#define OFF_W2S 32768
#define OFF_HP  49152
#define OFF_RP  53248
#define OFF_RED 57344
#define PERSIST_SMEM (57600 * 4)

// swizzled index into [256 kk][4 bp] float4 arrays (kills STS bank conflicts)
#define HPIDX(kk, bq) ((kk) * 4 + ((bq) ^ (((kk) >> 1) & 3)))
#define RIDX(jp, bq)  ((jp) * 4 + ((bq) ^ (((jp) >> 1) & 3)))

__global__ __launch_bounds__(128, 1)
void persist_kernel(const float* __restrict__ hiddens,
                    const float* __restrict__ W1,
                    const float* __restrict__ W2,
                    float* __restrict__ Yext,
                    float* __restrict__ hs_out,
                    int layer, int useY1) {
    extern __shared__ float sm[];
    float4* w1s = (float4*)sm;                 // [256 kk][32 jp]
    float4* w2s = (float4*)(sm + OFF_W2S);     // [256 kk][16 jp]
    float4* hp  = (float4*)(sm + OFF_HP);      // [256 kk][4 bp] swizzled
    float4* rp  = (float4*)(sm + OFF_RP);      // [256 kk][4 bp] swizzled
    float4* red = (float4*)(sm + OFF_RED);     // [16 jp][4 bp] swizzled
    const ulonglong2* hpu = (const ulonglong2*)hp;
    const ulonglong2* rpu = (const ulonglong2*)rp;

    int tid = threadIdx.x;
    int cg = blockIdx.x & 15, bg = blockIdx.x >> 4;
    int b0 = bg * 8;
    float* Y = useY1 ? g_y1 : Yext;
    const float* W1h = W1 + (size_t)layer * 1024 * 1024 + 512;
    const float* W2h = W2 + (size_t)layer * 512 * 1024 + 512;

    // ---- stage recurrent weights ONCE (k-pair interleaved, j-pairs packed) ----
    for (int idx = tid; idx < 8192; idx += 128) {
        int kk = idx & 255, jp = idx >> 8;
        const float* r = W1h + (size_t)(cg * 64 + 2 * jp) * 1024 + 2 * kk;
        float2 a = *(const float2*)r;
        float2 b = *(const float2*)(r + 1024);
        w1s[kk * 32 + jp] = make_float4(a.x, b.x, a.y, b.y);
    }
    for (int idx = tid; idx < 4096; idx += 128) {
        int kk = idx & 255, jp = idx >> 8;
        const float* r = W2h + (size_t)(cg * 32 + 2 * jp) * 1024 + 2 * kk;
        float2 a = *(const float2*)r;
        float2 b = *(const float2*)(r + 1024);
        w2s[kk * 16 + jp] = make_float4(a.x, b.x, a.y, b.y);
    }

    int bp  = tid & 3;          // batch pair: b = b0 + 2*bp, +1
    int jp1 = tid >> 2;         // 0..31 (phase1: 2 j each)
    int jp2 = jp1 & 15;         // 0..15 (phase2: 2 j each)
    int kh  = tid >> 6;         // 0/1 k-half split (phase2)
    int sense = 0;

    for (int t = 0; t < NT; t++) {
        // ---- stage h slice [8b x 512k] -> hp (pair interleaved) ----
        if (t == 0) {
            for (int i = tid; i < 1024; i += 128) {
                int kk = i & 255, bq = i >> 8;
                float2 v = *(const float2*)&hiddens[layer * 512 + 2 * kk];
                hp[HPIDX(kk, bq)] = make_float4(v.x, v.x, v.y, v.y);
            }
        } else {
            for (int i = tid; i < 1024; i += 128) {
                int kk = i & 255, bq = i >> 8;
                int b = b0 + 2 * bq;
                float2 e = __ldcg((const float2*)&g_h[b * 512 + 2 * kk]);
                float2 o = __ldcg((const float2*)&g_h[(b + 1) * 512 + 2 * kk]);
                hp[HPIDX(kk, bq)] = make_float4(e.x, o.x, e.y, o.y);
            }
        }
        __syncthreads();

        // ---- phase1: pre = Ax[t] + h @ W1h^T (64 cols of 1024) ----
        {
            unsigned long long a0 = 0ull, a1 = 0ull;
#pragma unroll 8
            for (int kk = 0; kk < 256; kk++) {
                float4 wv = w1s[kk * 32 + jp1];
                ulonglong2 hv = hpu[HPIDX(kk, bp)];   // (h_be,h_bo) k0 | k1
                fma2(a0, hv.x, pk2(wv.x, wv.x));
                fma2(a1, hv.x, pk2(wv.y, wv.y));
                fma2(a0, hv.y, pk2(wv.z, wv.z));
                fma2(a1, hv.y, pk2(wv.w, wv.w));
            }
            float2 v0 = up2(a0), v1 = up2(a1);        // (be,bo) for j0 | j1
            int j0 = cg * 64 + 2 * jp1;
            int be = b0 + 2 * bp, bo = be + 1;
            size_t re = ((size_t)t * 64 + be) * 1024 + j0;
            float2 axe = *(const float2*)&g_Ax[re];
            float2 axo = *(const float2*)&g_Ax[re + 1024];
            float sbe0 = sigf(v0.x + axe.x), sbe1 = sigf(v1.x + axe.y);
            float sbo0 = sigf(v0.y + axo.x), sbo1 = sigf(v1.y + axo.y);
            if (cg < 8) {        // r gate -> rh = r * h
                float4 hh = hp[HPIDX(cg * 32 + jp1, bp)];
                __stcg((float2*)&g_rh[be * 512 + j0], make_float2(sbe0 * hh.x, sbe1 * hh.z));
                __stcg((float2*)&g_rh[bo * 512 + j0], make_float2(sbo0 * hh.y, sbo1 * hh.w));
            } else {             // z gate
                int zj = j0 - 512;
                __stcg((float2*)&g_z[be * 512 + zj], make_float2(sbe0, sbe1));
                __stcg((float2*)&g_z[bo * 512 + zj], make_float2(sbo0, sbo1));
            }
        }
        sense ^= 1; grid_barrier(sense);

        // ---- stage rh slice -> rp ----
        for (int i = tid; i < 1024; i += 128) {
            int kk = i & 255, bq = i >> 8;
            int b = b0 + 2 * bq;
            float2 e = __ldcg((const float2*)&g_rh[b * 512 + 2 * kk]);
            float2 o = __ldcg((const float2*)&g_rh[(b + 1) * 512 + 2 * kk]);
            rp[HPIDX(kk, bq)] = make_float4(e.x, o.x, e.y, o.y);
        }
        __syncthreads();

        // ---- phase2: g = tanh(Gx + rh @ W2h^T); h = z*h + (1-z)*g ----
        {
            unsigned long long c0 = 0ull, c1 = 0ull;
            int kb = kh * 128;
#pragma unroll 8
            for (int q = 0; q < 128; q++) {
                int kk = kb + q;
                float4 wv = w2s[kk * 16 + jp2];
                ulonglong2 hv = rpu[HPIDX(kk, bp)];
                fma2(c0, hv.x, pk2(wv.x, wv.x));
                fma2(c1, hv.x, pk2(wv.y, wv.y));
                fma2(c0, hv.y, pk2(wv.z, wv.z));
                fma2(c1, hv.y, pk2(wv.w, wv.w));
            }
            if (kh == 1) {
                float2 u0 = up2(c0), u1 = up2(c1);
                red[RIDX(jp2, bp)] = make_float4(u0.x, u0.y, u1.x, u1.y);
            }
            __syncthreads();
            if (kh == 0) {
                float4 rv = red[RIDX(jp2, bp)];
                float2 u0 = up2(c0), u1 = up2(c1);
                float p_be0 = u0.x + rv.x, p_bo0 = u0.y + rv.y;
                float p_be1 = u1.x + rv.z, p_bo1 = u1.y + rv.w;
                int j0 = cg * 32 + 2 * jp2;
                int be = b0 + 2 * bp, bo = be + 1;
                size_t re = ((size_t)t * 64 + be) * 512 + j0;
                float2 gxe = *(const float2*)&g_Gx[re];
                float2 gxo = *(const float2*)&g_Gx[re + 512];
                float gbe0 = tanhf(p_be0 + gxe.x), gbe1 = tanhf(p_be1 + gxe.y);
                float gbo0 = tanhf(p_bo0 + gxo.x), gbo1 = tanhf(p_bo1 + gxo.y);
                float2 zbe = __ldcg((const float2*)&g_z[be * 512 + j0]);
                float2 zbo = __ldcg((const float2*)&g_z[bo * 512 + j0]);
                float4 hh = hp[HPIDX(cg * 16 + jp2, bp)];   // old h at (b, j0/j0+1)
                float hbe0 = zbe.x * hh.x + (1.0f - zbe.x) * gbe0;
                float hbe1 = zbe.y * hh.z + (1.0f - zbe.y) * gbe1;
                float hbo0 = zbo.x * hh.y + (1.0f - zbo.x) * gbo0;
                float hbo1 = zbo.y * hh.w + (1.0f - zbo.y) * gbo1;
                __stcg((float2*)&g_h[be * 512 + j0], make_float2(hbe0, hbe1));
                __stcg((float2*)&g_h[bo * 512 + j0], make_float2(hbo0, hbo1));
                *(float2*)&Y[re]       = make_float2(hbe0, hbe1);
                *(float2*)&Y[re + 512] = make_float2(hbo0, hbo1);
                if (t == NT - 1) {
                    *(float2*)&hs_out[be * 512 + j0] = make_float2(hbe0, hbe1);
                    *(float2*)&hs_out[bo * 512 + j0] = make_float2(hbo0, hbo1);
                }
            }
        }
        sense ^= 1; grid_barrier(sense);
    }
}

extern "C" void kernel_launch(void* const* d_in, const int* in_sizes, int n_in,
                              void* d_out, int out_size) {
    const float* x       = (const float*)d_in[0];  // [512,64,512]
    const float* hiddens = (const float*)d_in[1];  // [2,1,512]
    const float* W1      = (const float*)d_in[2];  // [2,1024,1024]
    const float* b1      = (const float*)d_in[3];  // [2,1024]
    const float* W2      = (const float*)d_in[4];  // [2,512,1024]
    const float* b2      = (const float*)d_in[5];  // [2,512]
    float* out = (float*)d_out;                    // out [T,B,512] then hs [2,B,512]
    float* hs_out = out + (size_t)NT * NB * NH;

    static int attr_done = 0;
    if (!attr_done) {
        cudaFuncSetAttribute(persist_kernel,
                             cudaFuncAttributeMaxDynamicSharedMemorySize, PERSIST_SMEM);
        attr_done = 1;
    }

    for (int layer = 0; layer < 2; layer++) {
        xproj_kernel<<<dim3(12, 256), 256>>>(x, W1, W2, b1, b2, layer, layer == 1);
        persist_kernel<<<NCTA, 128, PERSIST_SMEM>>>(
            hiddens, W1, W2, out, hs_out + (size_t)layer * NB * NH,
            layer, layer == 0);
    }
}